// round 13
// baseline (speedup 1.0000x reference)
#include <cuda_runtime.h>
#include <cuda_bf16.h>
#include <cstdint>

#define N_   1024
#define S_   144
#define R_   96
#define K_   128
#define D_   768
#define ABL_ 48
#define RK_  (R_ * K_)   // 12288
#define KSPLIT 6

// ---------------------------------------------------------------------------
// Device-global scratch
// ---------------------------------------------------------------------------
__device__ float g_c0[RK_];
__device__ __align__(16) __nv_bfloat16 g_blh[(size_t)R_ * K_ * D_];
__device__ __align__(16) __nv_bfloat16 g_bll[(size_t)R_ * K_ * D_];
__device__ __align__(16) __nv_bfloat16 g_chi[(size_t)N_ * RK_];
__device__ __align__(16) __nv_bfloat16 g_clo[(size_t)N_ * RK_];
__device__ __align__(16) __nv_bfloat16 g_ibth[(size_t)D_ * RK_];
__device__ __align__(16) __nv_bfloat16 g_ibtl[(size_t)D_ * RK_];
__device__ float g_part[(size_t)KSPLIT * N_ * D_];

// ---------------------------------------------------------------------------
// Helpers
// ---------------------------------------------------------------------------
__device__ __forceinline__ uint32_t smem_u32(const void* p) {
    uint32_t a;
    asm("{ .reg .u64 t; cvta.to.shared.u64 t, %1; cvt.u32.u64 %0, t; }"
        : "=r"(a) : "l"(p));
    return a;
}

__device__ __forceinline__ void cp16(uint32_t dst, const void* src) {
    asm volatile("cp.async.cg.shared.global [%0], [%1], 16;" :: "r"(dst), "l"(src));
}
#define CP_COMMIT() asm volatile("cp.async.commit_group;" ::: "memory")
#define CP_WAIT0()  asm volatile("cp.async.wait_group 0;"  ::: "memory")

__device__ __forceinline__ void ldsm4(uint32_t* r, uint32_t a) {
    asm volatile("ldmatrix.sync.aligned.m8n8.x4.shared.b16 {%0,%1,%2,%3}, [%4];"
        : "=r"(r[0]), "=r"(r[1]), "=r"(r[2]), "=r"(r[3]) : "r"(a));
}

__device__ __forceinline__ void mma_bf16(float* d, const uint32_t* a, const uint32_t* b) {
    asm volatile(
        "mma.sync.aligned.m16n8k16.row.col.f32.bf16.bf16.f32 "
        "{%0,%1,%2,%3}, {%4,%5,%6,%7}, {%8,%9}, {%0,%1,%2,%3};"
        : "+f"(d[0]), "+f"(d[1]), "+f"(d[2]), "+f"(d[3])
        : "r"(a[0]), "r"(a[1]), "r"(a[2]), "r"(a[3]), "r"(b[0]), "r"(b[1]));
}

__device__ __forceinline__ void split1(float v, __nv_bfloat16& h, __nv_bfloat16& l) {
    h = __float2bfloat16(v);
    l = __float2bfloat16(v - __bfloat162float(h));
}
__device__ __forceinline__ uint32_t pack2(__nv_bfloat16 a, __nv_bfloat16 b) {
    uint16_t x = *(uint16_t*)&a, y = *(uint16_t*)&b;
    return (uint32_t)x | ((uint32_t)y << 16);
}

// truncation split pair helpers: (v0, v1) -> packed bf16x2 (lo half = v0)
__device__ __forceinline__ uint32_t hi_pair(float v0, float v1) {
    uint32_t r;
    asm("prmt.b32 %0, %1, %2, 0x7632;" : "=r"(r)
        : "r"(__float_as_uint(v0)), "r"(__float_as_uint(v1)));
    return r;
}
__device__ __forceinline__ uint32_t lo_pair(float v0, float v1) {
    float t0 = __uint_as_float(__float_as_uint(v0) & 0xFFFF0000u);
    float t1 = __uint_as_float(__float_as_uint(v1) & 0xFFFF0000u);
    float l0 = v0 - t0, l1 = v1 - t1;
    uint32_t r;
    asm("cvt.rn.bf16x2.f32 %0, %1, %2;" : "=r"(r) : "f"(l1), "f"(l0));
    return r;
}

// 64B-row swizzle (32 bf16/row): phys chunk = ch ^ ((row>>1)&3)
#define SW1(rw, ch4) ((rw) * 64 + (((ch4) ^ (((rw) >> 1) & 3)) << 4))
// 128B-row swizzle (64 bf16/row): phys chunk = ch ^ (row&7)
#define SW2(rw, ch8) ((rw) * 128 + (((ch8) ^ ((rw) & 7)) << 4))

// GEMM1 smem: A 256x32 bf16 (16KB) hi/lo + B 128x32 bf16 (8KB) hi/lo
#define A1T 16384
#define B1T 8192
#define STG1_BYTES (2 * A1T + 2 * B1T)   // 49152
#define SMEM_G1 (2 * STG1_BYTES)         // 98304
// GEMM2 smem: A 256x64 (32KB) hi/lo + B 128x64 (16KB) hi/lo
#define A2T 32768
#define B2T 16384
#define STG2_BYTES (2 * A2T + 2 * B2T)   // 98304
#define SMEM_G2 (2 * STG2_BYTES)         // 196608

// ---------------------------------------------------------------------------
// prep + blam convert fused
// ---------------------------------------------------------------------------
__global__ void prep_blam(const float* __restrict__ lambdas,
                          const float* __restrict__ bases,
                          const float* __restrict__ means,
                          const int*   __restrict__ lengths,
                          int total_lam) {
    int r = blockIdx.x, tid = threadIdx.x;

    __shared__ float smean[D_];
    __shared__ float slam[K_];
    __shared__ float sdot[256];

    for (int d = tid; d < D_; d += 256)
        smean[d] = means[r * D_ + d];
    __syncthreads();

    int off = 0;
    for (int i = 0; i < r; i++) off += lengths[i];
    int len = lengths[r];

    int k = tid >> 1, h = tid & 1;
    const float* brow = bases + ((size_t)r * K_ + k) * D_;
    float dot = 0.0f;
    #pragma unroll 8
    for (int d = h * (D_ / 2); d < (h + 1) * (D_ / 2); d++)
        dot += smean[d] * brow[d];
    sdot[tid] = dot;
    __syncthreads();

    if (h == 0) {
        float lam = 0.0f;
        if (k < len) {
            int idx = off + k;
            if (idx > total_lam - 1) idx = total_lam - 1;
            lam = lambdas[idx];
        }
        g_c0[r * K_ + k] = lam * (sdot[tid] + sdot[tid + 1]);
        slam[k] = lam;
    }
    __syncthreads();

    const float* bbase = bases + (size_t)r * K_ * D_;
    for (int i4 = tid * 4; i4 < K_ * D_; i4 += 256 * 4) {
        float lam = slam[i4 / D_];
        float4 v = *(const float4*)(bbase + i4);
        __align__(8) __nv_bfloat16 hh[4], ll[4];
        split1(v.x * lam, hh[0], ll[0]); split1(v.y * lam, hh[1], ll[1]);
        split1(v.z * lam, hh[2], ll[2]); split1(v.w * lam, hh[3], ll[3]);
        size_t o = (size_t)r * K_ * D_ + i4;
        *(uint2*)(g_blh + o) = *(uint2*)hh;
        *(uint2*)(g_bll + o) = *(uint2*)ll;
    }
}

// invb [j][d] -> transposed bf16 hi/lo [d][j]
__global__ void convert_ibt(const float* __restrict__ invb) {
    __shared__ float t[32][33];
    int jb = blockIdx.x * 32, db = blockIdx.y * 32;
    int tx = threadIdx.x, ty = threadIdx.y;  // 32 x 8
    #pragma unroll
    for (int k = 0; k < 4; k++)
        t[ty + 8 * k][tx] = invb[(size_t)(jb + ty + 8 * k) * D_ + db + tx];
    __syncthreads();
    #pragma unroll
    for (int k = 0; k < 4; k++) {
        float v = t[tx][ty + 8 * k];
        __nv_bfloat16 h, l;
        split1(v, h, l);
        size_t o = (size_t)(db + ty + 8 * k) * RK_ + jb + tx;
        g_ibth[o] = h;
        g_ibtl[o] = l;
    }
}

// ablated-slice sum -> out
__global__ void abl_kernel(const float* __restrict__ x,
                           const int* __restrict__ abl,
                           float* __restrict__ out) {
    __shared__ int sabl[ABL_];
    if (threadIdx.x < ABL_) sabl[threadIdx.x] = abl[threadIdx.x];
    __syncthreads();

    size_t i4 = ((size_t)blockIdx.x * blockDim.x + threadIdx.x) * 4;
    int n = (int)(i4 / D_);
    int d = (int)(i4 - (size_t)n * D_);
    const float* xp = x + (size_t)n * S_ * D_ + d;

    float4 s = make_float4(0.f, 0.f, 0.f, 0.f);
    #pragma unroll
    for (int a = 0; a < ABL_; a++) {
        float4 v = __ldg((const float4*)(xp + (size_t)sabl[a] * D_));
        s.x += v.x; s.y += v.y; s.z += v.z; s.w += v.w;
    }
    *(float4*)(out + i4) = s;
}

// ---------------------------------------------------------------------------
// GEMM1 (mma.sync bf16x3, fused gather + truncation split):
// Block 256(m=n) x 128(n=k) x BK=32. grid=(4, 96), 512 thr, 16 warps 4x4.
// ---------------------------------------------------------------------------
#define G1_NC 24

__global__ __launch_bounds__(512)
void gemm1_mma(const float* __restrict__ x, const int* __restrict__ resid) {
    extern __shared__ __align__(128) char sm[];
    uint32_t sbase = smem_u32(sm);
    int tid = threadIdx.x, lane = tid & 31, wid = tid >> 5;
    int r = blockIdx.y, n0 = blockIdx.x * 256;
    int s = __ldg(resid + r);
    int wm = (wid >> 2) * 64, wn = (wid & 3) * 32;

    const float* Ax = x + ((size_t)n0 * S_ + s) * D_;
    const __nv_bfloat16* Bh = g_blh + (size_t)r * K_ * D_;
    const __nv_bfloat16* Bl = g_bll + (size_t)r * K_ * D_;

    float acc[4][4][4];
    #pragma unroll
    for (int a = 0; a < 4; a++)
        #pragma unroll
        for (int b = 0; b < 4; b++)
            #pragma unroll
            for (int c = 0; c < 4; c++) acc[a][b][c] = 0.0f;

    int frow = tid >> 1, fhalf = tid & 1;   // A: row 0..255, 16-col half
    int brow = tid >> 2, bch = tid & 3;     // B: row 0..127, 16B chunk
    float4 ra[4];

    auto ldgA = [&](int c) {
        const float* p = Ax + (size_t)frow * (S_ * D_) + c * 32 + fhalf * 16;
        #pragma unroll
        for (int i = 0; i < 4; i++) ra[i] = __ldg((const float4*)p + i);
    };

    auto stsA = [&](int stg) {
        char* b = sm + stg * STG1_BYTES;
        uint32_t h[8], l[8];
        #pragma unroll
        for (int i = 0; i < 4; i++) {
            h[2*i]   = hi_pair(ra[i].x, ra[i].y);
            h[2*i+1] = hi_pair(ra[i].z, ra[i].w);
            l[2*i]   = lo_pair(ra[i].x, ra[i].y);
            l[2*i+1] = lo_pair(ra[i].z, ra[i].w);
        }
        uint32_t off0 = SW1(frow, fhalf * 2);
        uint32_t off1 = SW1(frow, fhalf * 2 + 1);
        *(uint4*)(b + off0)       = make_uint4(h[0], h[1], h[2], h[3]);
        *(uint4*)(b + off1)       = make_uint4(h[4], h[5], h[6], h[7]);
        *(uint4*)(b + A1T + off0) = make_uint4(l[0], l[1], l[2], l[3]);
        *(uint4*)(b + A1T + off1) = make_uint4(l[4], l[5], l[6], l[7]);
    };

    auto cpB = [&](int c, int stg) {
        uint32_t b = sbase + stg * STG1_BYTES;
        uint32_t off = SW1(brow, bch);
        size_t so = (size_t)brow * D_ + c * 32 + bch * 8;
        cp16(b + 2 * A1T + off,       Bh + so);
        cp16(b + 2 * A1T + B1T + off, Bl + so);
    };

    auto compute = [&](int stg) {
        uint32_t b = sbase + stg * STG1_BYTES;
        #pragma unroll
        for (int kk = 0; kk < 2; kk++) {
            int lc = kk * 2 + (lane >> 4);
            uint32_t bh[4][2], bl[4][2];
            #pragma unroll
            for (int bi = 0; bi < 2; bi++) {
                int rw = wn + bi * 16 + (lane & 15);
                uint32_t off = SW1(rw, lc);
                uint32_t t[4];
                ldsm4(t, b + 2 * A1T + off);
                bh[2*bi][0] = t[0]; bh[2*bi][1] = t[2];
                bh[2*bi+1][0] = t[1]; bh[2*bi+1][1] = t[3];
                ldsm4(t, b + 2 * A1T + B1T + off);
                bl[2*bi][0] = t[0]; bl[2*bi][1] = t[2];
                bl[2*bi+1][0] = t[1]; bl[2*bi+1][1] = t[3];
            }
            #pragma unroll
            for (int mi = 0; mi < 4; mi++) {
                int rw = wm + mi * 16 + (lane & 15);
                uint32_t off = SW1(rw, lc);
                uint32_t ah[4], al[4];
                ldsm4(ah, b + off);
                ldsm4(al, b + A1T + off);
                #pragma unroll
                for (int ni = 0; ni < 4; ni++) {
                    mma_bf16(acc[mi][ni], ah, bh[ni]);
                    mma_bf16(acc[mi][ni], ah, bl[ni]);
                    mma_bf16(acc[mi][ni], al, bh[ni]);
                }
            }
        }
    };

    // prologue
    ldgA(0); stsA(0); cpB(0, 0); CP_COMMIT();
    ldgA(1);

    #pragma unroll 1
    for (int c = 0; c < G1_NC; c++) {
        CP_WAIT0();
        __syncthreads();
        if (c + 1 < G1_NC) {
            int stg = (c + 1) & 1;
            stsA(stg);
            cpB(c + 1, stg); CP_COMMIT();
            if (c + 2 < G1_NC) ldgA(c + 2);
        }
        compute(c & 1);
    }

    int mrow = lane >> 2, kcol = (lane & 3) * 2;
    #pragma unroll
    for (int mi = 0; mi < 4; mi++)
        #pragma unroll
        for (int ni = 0; ni < 4; ni++) {
            int kg = wn + ni * 8 + kcol;
            float c00 = g_c0[r * K_ + kg], c01 = g_c0[r * K_ + kg + 1];
            int m0 = n0 + wm + mi * 16 + mrow;
            #pragma unroll
            for (int half = 0; half < 2; half++) {
                float v0 = acc[mi][ni][half * 2 + 0] - c00;
                float v1 = acc[mi][ni][half * 2 + 1] - c01;
                __nv_bfloat16 h0, l0, h1, l1;
                split1(v0, h0, l0);
                split1(v1, h1, l1);
                size_t o = (size_t)(m0 + half * 8) * RK_ + r * K_ + kg;
                *(uint32_t*)(g_chi + o) = pack2(h0, h1);
                *(uint32_t*)(g_clo + o) = pack2(l0, l1);
            }
        }
}

// ---------------------------------------------------------------------------
// GEMM2 (mma.sync bf16x3): BK=64, 2-stage, one sync per chunk.
// Block 256(n) x 128(d), split-K=6. grid=(4,6,6)=144 CTAs. 512 thr.
// ---------------------------------------------------------------------------
__global__ __launch_bounds__(512)
void gemm2_mma() {
    extern __shared__ __align__(128) char sm[];
    uint32_t sbase = smem_u32(sm);
    int tid = threadIdx.x, lane = tid & 31, wid = tid >> 5;
    int n0 = blockIdx.x * 256, d0 = blockIdx.y * 128, ks = blockIdx.z;
    int jbase = ks * (RK_ / KSPLIT);
    int wm = (wid >> 2) * 64, wn = (wid & 3) * 32;

    const __nv_bfloat16* Ah = g_chi  + (size_t)n0 * RK_ + jbase;
    const __nv_bfloat16* Al = g_clo  + (size_t)n0 * RK_ + jbase;
    const __nv_bfloat16* Bh = g_ibth + (size_t)d0 * RK_ + jbase;
    const __nv_bfloat16* Bl = g_ibtl + (size_t)d0 * RK_ + jbase;

    float acc[4][4][4];
    #pragma unroll
    for (int a = 0; a < 4; a++)
        #pragma unroll
        for (int b = 0; b < 4; b++)
            #pragma unroll
            for (int c = 0; c < 4; c++) acc[a][b][c] = 0.0f;

    int rw0 = tid >> 3, fch = tid & 7;

    auto fill = [&](int c, int stg) {
        uint32_t b = sbase + stg * STG2_BYTES;
        int j0 = c * 64;
        #pragma unroll
        for (int i = 0; i < 4; i++) {
            int rw = rw0 + 64 * i;
            uint32_t off = SW2(rw, fch);
            size_t so = (size_t)rw * RK_ + j0 + fch * 8;
            cp16(b +       off, Ah + so);
            cp16(b + A2T + off, Al + so);
        }
        #pragma unroll
        for (int i = 0; i < 2; i++) {
            int rw = rw0 + 64 * i;
            uint32_t off = SW2(rw, fch);
            size_t so = (size_t)rw * RK_ + j0 + fch * 8;
            cp16(b + 2 * A2T +       off, Bh + so);
            cp16(b + 2 * A2T + B2T + off, Bl + so);
        }
    };

    auto compute = [&](int stg) {
        uint32_t b = sbase + stg * STG2_BYTES;
        #pragma unroll
        for (int kk = 0; kk < 4; kk++) {
            int lc = kk * 2 + (lane >> 4);
            uint32_t bh[4][2], bl[4][2];
            #pragma unroll
            for (int bi = 0; bi < 2; bi++) {
                int rw = wn + bi * 16 + (lane & 15);
                uint32_t off = SW2(rw, lc);
                uint32_t t[4];
                ldsm4(t, b + 2 * A2T + off);
                bh[2*bi][0] = t[0]; bh[2*bi][1] = t[2];
                bh[2*bi+1][0] = t[1]; bh[2*bi+1][1] = t[3];
                ldsm4(t, b + 2 * A2T + B2T + off);
                bl[2*bi][0] = t[0]; bl[2*bi][1] = t[2];
                bl[2*bi+1][0] = t[1]; bl[2*bi+1][1] = t[3];
            }
            #pragma unroll
            for (int mi = 0; mi < 4; mi++) {
                int rw = wm + mi * 16 + (lane & 15);
                uint32_t off = SW2(rw, lc);
                uint32_t ah[4], al[4];
                ldsm4(ah, b + off);
                ldsm4(al, b + A2T + off);
                #pragma unroll
                for (int ni = 0; ni < 4; ni++) {
                    mma_bf16(acc[mi][ni], ah, bh[ni]);
                    mma_bf16(acc[mi][ni], ah, bl[ni]);
                    mma_bf16(acc[mi][ni], al, bh[ni]);
                }
            }
        }
    };

    const int NC = (RK_ / KSPLIT) / 64;   // 32
    fill(0, 0); CP_COMMIT();
    #pragma unroll 1
    for (int c = 0; c < NC; c++) {
        CP_WAIT0();
        __syncthreads();
        if (c + 1 < NC) { fill(c + 1, (c + 1) & 1); CP_COMMIT(); }
        compute(c & 1);
    }

    int mrow = lane >> 2, kcol = (lane & 3) * 2;
    #pragma unroll
    for (int mi = 0; mi < 4; mi++)
        #pragma unroll
        for (int ni = 0; ni < 4; ni++) {
            int dg = d0 + wn + ni * 8 + kcol;
            int m0 = n0 + wm + mi * 16 + mrow;
            #pragma unroll
            for (int half = 0; half < 2; half++) {
                float2 v = make_float2(acc[mi][ni][half * 2 + 0],
                                       acc[mi][ni][half * 2 + 1]);
                *(float2*)(g_part + ((size_t)ks * N_ + m0 + half * 8) * D_ + dg) = v;
            }
        }
}

// out += sum of KSPLIT partials
__global__ void reduce_out(float* __restrict__ out) {
    size_t i4 = ((size_t)blockIdx.x * blockDim.x + threadIdx.x) * 4;
    float4 o = *(float4*)(out + i4);
    #pragma unroll
    for (int ks = 0; ks < KSPLIT; ks++) {
        float4 p = *(const float4*)(g_part + (size_t)ks * N_ * D_ + i4);
        o.x += p.x; o.y += p.y; o.z += p.z; o.w += p.w;
    }
    *(float4*)(out + i4) = o;
}

// ---------------------------------------------------------------------------
// Launch (gemm1 stays the 4th launch -> profiled)
// ---------------------------------------------------------------------------
extern "C" void kernel_launch(void* const* d_in, const int* in_sizes, int n_in,
                              void* d_out, int out_size) {
    const float* x       = (const float*)d_in[0];
    const float* lambdas = (const float*)d_in[1];
    const float* bases   = (const float*)d_in[2];
    const float* invb    = (const float*)d_in[3];
    const float* means   = (const float*)d_in[4];
    const int*   resid   = (const int*)d_in[5];
    const int*   abl     = (const int*)d_in[6];
    const int*   lengths = (const int*)d_in[7];
    float*       out     = (float*)d_out;

    int total_lam = in_sizes[1];

    cudaFuncSetAttribute(gemm1_mma, cudaFuncAttributeMaxDynamicSharedMemorySize, SMEM_G1);
    cudaFuncSetAttribute(gemm2_mma, cudaFuncAttributeMaxDynamicSharedMemorySize, SMEM_G2);

    prep_blam<<<R_, 256>>>(lambdas, bases, means, lengths, total_lam);
    convert_ibt<<<dim3(RK_ / 32, D_ / 32), dim3(32, 8)>>>(invb);
    abl_kernel<<<(N_ * D_ / 4) / 256, 256>>>(x, abl, out);
    gemm1_mma<<<dim3(N_ / 256, R_), 512, SMEM_G1>>>(x, resid);
    gemm2_mma<<<dim3(N_ / 256, D_ / 128, KSPLIT), 512, SMEM_G2>>>();
    reduce_out<<<(N_ * D_ / 4) / 256, 256>>>(out);
}

// round 14
// speedup vs baseline: 1.0544x; 1.0544x over previous
#include <cuda_runtime.h>
#include <cuda_bf16.h>
#include <cstdint>

#define N_   1024
#define S_   144
#define R_   96
#define K_   128
#define D_   768
#define ABL_ 48
#define RK_  (R_ * K_)   // 12288
#define KSPLIT 6

// ---------------------------------------------------------------------------
// Device-global scratch
// ---------------------------------------------------------------------------
__device__ float g_c0[RK_];
__device__ __align__(16) __nv_bfloat16 g_blh[(size_t)R_ * K_ * D_];
__device__ __align__(16) __nv_bfloat16 g_bll[(size_t)R_ * K_ * D_];
__device__ __align__(16) __nv_bfloat16 g_chi[(size_t)N_ * RK_];
__device__ __align__(16) __nv_bfloat16 g_clo[(size_t)N_ * RK_];
__device__ __align__(16) __nv_bfloat16 g_ibth[(size_t)D_ * RK_];
__device__ __align__(16) __nv_bfloat16 g_ibtl[(size_t)D_ * RK_];
__device__ float g_part[(size_t)KSPLIT * N_ * D_];

// ---------------------------------------------------------------------------
// Helpers
// ---------------------------------------------------------------------------
__device__ __forceinline__ uint32_t smem_u32(const void* p) {
    uint32_t a;
    asm("{ .reg .u64 t; cvta.to.shared.u64 t, %1; cvt.u32.u64 %0, t; }"
        : "=r"(a) : "l"(p));
    return a;
}

__device__ __forceinline__ void cp16(uint32_t dst, const void* src) {
    asm volatile("cp.async.cg.shared.global [%0], [%1], 16;" :: "r"(dst), "l"(src));
}
#define CP_COMMIT() asm volatile("cp.async.commit_group;" ::: "memory")
#define CP_WAIT0()  asm volatile("cp.async.wait_group 0;"  ::: "memory")

__device__ __forceinline__ void ldsm4(uint32_t* r, uint32_t a) {
    asm volatile("ldmatrix.sync.aligned.m8n8.x4.shared.b16 {%0,%1,%2,%3}, [%4];"
        : "=r"(r[0]), "=r"(r[1]), "=r"(r[2]), "=r"(r[3]) : "r"(a));
}

__device__ __forceinline__ void mma_bf16(float* d, const uint32_t* a, const uint32_t* b) {
    asm volatile(
        "mma.sync.aligned.m16n8k16.row.col.f32.bf16.bf16.f32 "
        "{%0,%1,%2,%3}, {%4,%5,%6,%7}, {%8,%9}, {%0,%1,%2,%3};"
        : "+f"(d[0]), "+f"(d[1]), "+f"(d[2]), "+f"(d[3])
        : "r"(a[0]), "r"(a[1]), "r"(a[2]), "r"(a[3]), "r"(b[0]), "r"(b[1]));
}

__device__ __forceinline__ void split1(float v, __nv_bfloat16& h, __nv_bfloat16& l) {
    h = __float2bfloat16(v);
    l = __float2bfloat16(v - __bfloat162float(h));
}
__device__ __forceinline__ uint32_t pack2(__nv_bfloat16 a, __nv_bfloat16 b) {
    uint16_t x = *(uint16_t*)&a, y = *(uint16_t*)&b;
    return (uint32_t)x | ((uint32_t)y << 16);
}

// truncation split pair helpers: (v0, v1) -> packed bf16x2 (lo half = v0)
__device__ __forceinline__ uint32_t hi_pair(float v0, float v1) {
    uint32_t r;
    asm("prmt.b32 %0, %1, %2, 0x7632;" : "=r"(r)
        : "r"(__float_as_uint(v0)), "r"(__float_as_uint(v1)));
    return r;
}
__device__ __forceinline__ uint32_t lo_pair(float v0, float v1) {
    float t0 = __uint_as_float(__float_as_uint(v0) & 0xFFFF0000u);
    float t1 = __uint_as_float(__float_as_uint(v1) & 0xFFFF0000u);
    float l0 = v0 - t0, l1 = v1 - t1;
    uint32_t r;
    asm("cvt.rn.bf16x2.f32 %0, %1, %2;" : "=r"(r) : "f"(l1), "f"(l0));
    return r;
}

// 64B-row swizzle (32 bf16/row): phys chunk = ch ^ ((row>>1)&3)
#define SW1(rw, ch4) ((rw) * 64 + (((ch4) ^ (((rw) >> 1) & 3)) << 4))
// 128B-row swizzle (64 bf16/row): phys chunk = ch ^ (row&7)
#define SW2(rw, ch8) ((rw) * 128 + (((ch8) ^ ((rw) & 7)) << 4))

// GEMM1 smem: 128x32 tiles, Ah|Al|Bh|Bl @ 8KB, 2 stages = 64KB -> 2 CTAs/SM
#define TILE_BYTES 8192
#define STG_BYTES  32768
#define SMEM_G1 (2 * STG_BYTES)
// GEMM2 smem: A 256x64 (32KB) hi/lo + B 128x64 (16KB) hi/lo, 2 stages
#define A2T 32768
#define B2T 16384
#define STG2_BYTES (2 * A2T + 2 * B2T)   // 98304
#define SMEM_G2 (2 * STG2_BYTES)         // 196608

// ---------------------------------------------------------------------------
// prep + blam convert fused
// ---------------------------------------------------------------------------
__global__ void prep_blam(const float* __restrict__ lambdas,
                          const float* __restrict__ bases,
                          const float* __restrict__ means,
                          const int*   __restrict__ lengths,
                          int total_lam) {
    int r = blockIdx.x, tid = threadIdx.x;

    __shared__ float smean[D_];
    __shared__ float slam[K_];
    __shared__ float sdot[256];

    for (int d = tid; d < D_; d += 256)
        smean[d] = means[r * D_ + d];
    __syncthreads();

    int off = 0;
    for (int i = 0; i < r; i++) off += lengths[i];
    int len = lengths[r];

    int k = tid >> 1, h = tid & 1;
    const float* brow = bases + ((size_t)r * K_ + k) * D_;
    float dot = 0.0f;
    #pragma unroll 8
    for (int d = h * (D_ / 2); d < (h + 1) * (D_ / 2); d++)
        dot += smean[d] * brow[d];
    sdot[tid] = dot;
    __syncthreads();

    if (h == 0) {
        float lam = 0.0f;
        if (k < len) {
            int idx = off + k;
            if (idx > total_lam - 1) idx = total_lam - 1;
            lam = lambdas[idx];
        }
        g_c0[r * K_ + k] = lam * (sdot[tid] + sdot[tid + 1]);
        slam[k] = lam;
    }
    __syncthreads();

    const float* bbase = bases + (size_t)r * K_ * D_;
    for (int i4 = tid * 4; i4 < K_ * D_; i4 += 256 * 4) {
        float lam = slam[i4 / D_];
        float4 v = *(const float4*)(bbase + i4);
        __align__(8) __nv_bfloat16 hh[4], ll[4];
        split1(v.x * lam, hh[0], ll[0]); split1(v.y * lam, hh[1], ll[1]);
        split1(v.z * lam, hh[2], ll[2]); split1(v.w * lam, hh[3], ll[3]);
        size_t o = (size_t)r * K_ * D_ + i4;
        *(uint2*)(g_blh + o) = *(uint2*)hh;
        *(uint2*)(g_bll + o) = *(uint2*)ll;
    }
}

// invb [j][d] -> transposed bf16 hi/lo [d][j]
__global__ void convert_ibt(const float* __restrict__ invb) {
    __shared__ float t[32][33];
    int jb = blockIdx.x * 32, db = blockIdx.y * 32;
    int tx = threadIdx.x, ty = threadIdx.y;  // 32 x 8
    #pragma unroll
    for (int k = 0; k < 4; k++)
        t[ty + 8 * k][tx] = invb[(size_t)(jb + ty + 8 * k) * D_ + db + tx];
    __syncthreads();
    #pragma unroll
    for (int k = 0; k < 4; k++) {
        float v = t[tx][ty + 8 * k];
        __nv_bfloat16 h, l;
        split1(v, h, l);
        size_t o = (size_t)(db + ty + 8 * k) * RK_ + jb + tx;
        g_ibth[o] = h;
        g_ibtl[o] = l;
    }
}

// ---------------------------------------------------------------------------
// GEMM1 (mma.sync bf16x3, fused gather + truncation split, 2-stage, 2 CTAs/SM)
// Block 128(m) x 128(k) x BK=32. grid=(8, 96), 256 thr, 8 warps 2x4.
// ---------------------------------------------------------------------------
#define G1_NC 24

__global__ __launch_bounds__(256, 2)
void gemm1_mma(const float* __restrict__ x, const int* __restrict__ resid) {
    extern __shared__ __align__(128) char sm[];
    uint32_t sbase = smem_u32(sm);
    int tid = threadIdx.x, lane = tid & 31, wid = tid >> 5;
    int r = blockIdx.y, n0 = blockIdx.x * 128;
    int s = __ldg(resid + r);
    int wm = (wid >> 2) * 64, wn = (wid & 3) * 32;

    const float* Ax = x + ((size_t)n0 * S_ + s) * D_;
    const __nv_bfloat16* Bh = g_blh + (size_t)r * K_ * D_;
    const __nv_bfloat16* Bl = g_bll + (size_t)r * K_ * D_;

    float acc[4][4][4];
    #pragma unroll
    for (int a = 0; a < 4; a++)
        #pragma unroll
        for (int b = 0; b < 4; b++)
            #pragma unroll
            for (int c = 0; c < 4; c++) acc[a][b][c] = 0.0f;

    int frow = tid >> 2, fch = tid & 3;
    float4 ra[4];

    auto ldgA = [&](int c) {
        int d0 = c * 32;
        #pragma unroll
        for (int i = 0; i < 2; i++) {
            int rw = frow + 64 * i;
            const float* p = Ax + (size_t)rw * (S_ * D_) + d0 + fch * 8;
            ra[2 * i]     = __ldg((const float4*)p);
            ra[2 * i + 1] = __ldg((const float4*)(p + 4));
        }
    };

    auto stsA = [&](int stg) {
        char* b = sm + stg * STG_BYTES;
        #pragma unroll
        for (int i = 0; i < 2; i++) {
            int rw = frow + 64 * i;
            uint32_t off = SW1(rw, fch);
            float4 v0 = ra[2 * i], v1 = ra[2 * i + 1];
            uint4 hq = make_uint4(hi_pair(v0.x, v0.y), hi_pair(v0.z, v0.w),
                                  hi_pair(v1.x, v1.y), hi_pair(v1.z, v1.w));
            uint4 lq = make_uint4(lo_pair(v0.x, v0.y), lo_pair(v0.z, v0.w),
                                  lo_pair(v1.x, v1.y), lo_pair(v1.z, v1.w));
            *(uint4*)(b + off)              = hq;
            *(uint4*)(b + TILE_BYTES + off) = lq;
        }
    };

    auto cpB = [&](int c, int stg) {
        uint32_t b = sbase + stg * STG_BYTES;
        int d0 = c * 32;
        #pragma unroll
        for (int i = 0; i < 2; i++) {
            int rw = frow + 64 * i;
            uint32_t off = SW1(rw, fch);
            size_t so = (size_t)rw * D_ + d0 + fch * 8;
            cp16(b + 2 * TILE_BYTES + off, Bh + so);
            cp16(b + 3 * TILE_BYTES + off, Bl + so);
        }
    };

    auto compute = [&](int stg) {
        uint32_t b = sbase + stg * STG_BYTES;
        #pragma unroll
        for (int kk = 0; kk < 2; kk++) {
            int lc = kk * 2 + (lane >> 4);
            uint32_t bh[4][2], bl[4][2];
            #pragma unroll
            for (int bi = 0; bi < 2; bi++) {
                int rw = wn + bi * 16 + (lane & 15);
                uint32_t off = SW1(rw, lc);
                uint32_t t[4];
                ldsm4(t, b + 2 * TILE_BYTES + off);
                bh[2*bi][0] = t[0]; bh[2*bi][1] = t[2];
                bh[2*bi+1][0] = t[1]; bh[2*bi+1][1] = t[3];
                ldsm4(t, b + 3 * TILE_BYTES + off);
                bl[2*bi][0] = t[0]; bl[2*bi][1] = t[2];
                bl[2*bi+1][0] = t[1]; bl[2*bi+1][1] = t[3];
            }
            #pragma unroll
            for (int mi = 0; mi < 4; mi++) {
                int rw = wm + mi * 16 + (lane & 15);
                uint32_t off = SW1(rw, lc);
                uint32_t ah[4], al[4];
                ldsm4(ah, b + off);
                ldsm4(al, b + TILE_BYTES + off);
                #pragma unroll
                for (int ni = 0; ni < 4; ni++) {
                    mma_bf16(acc[mi][ni], ah, bh[ni]);
                    mma_bf16(acc[mi][ni], ah, bl[ni]);
                    mma_bf16(acc[mi][ni], al, bh[ni]);
                }
            }
        }
    };

    // prologue: stage 0 filled; regs hold chunk 1
    ldgA(0); stsA(0); cpB(0, 0); CP_COMMIT();
    ldgA(1);

    #pragma unroll 1
    for (int c = 0; c < G1_NC; c++) {
        CP_WAIT0();
        __syncthreads();
        if (c + 1 < G1_NC) {
            int stg = (c + 1) & 1;
            stsA(stg);
            cpB(c + 1, stg); CP_COMMIT();
            if (c + 2 < G1_NC) ldgA(c + 2);
        }
        compute(c & 1);
    }

    int mrow = lane >> 2, kcol = (lane & 3) * 2;
    #pragma unroll
    for (int mi = 0; mi < 4; mi++)
        #pragma unroll
        for (int ni = 0; ni < 4; ni++) {
            int kg = wn + ni * 8 + kcol;
            float c00 = g_c0[r * K_ + kg], c01 = g_c0[r * K_ + kg + 1];
            int m0 = n0 + wm + mi * 16 + mrow;
            #pragma unroll
            for (int half = 0; half < 2; half++) {
                float v0 = acc[mi][ni][half * 2 + 0] - c00;
                float v1 = acc[mi][ni][half * 2 + 1] - c01;
                __nv_bfloat16 h0, l0, h1, l1;
                split1(v0, h0, l0);
                split1(v1, h1, l1);
                size_t o = (size_t)(m0 + half * 8) * RK_ + r * K_ + kg;
                *(uint32_t*)(g_chi + o) = pack2(h0, h1);
                *(uint32_t*)(g_clo + o) = pack2(l0, l1);
            }
        }
}

// ---------------------------------------------------------------------------
// GEMM2 (mma.sync bf16x3): BK=64, 2-stage, one sync per chunk.
// Block 256(n) x 128(d), split-K=6. grid=(4,6,6)=144 CTAs. 512 thr.
// ---------------------------------------------------------------------------
__global__ __launch_bounds__(512)
void gemm2_mma() {
    extern __shared__ __align__(128) char sm[];
    uint32_t sbase = smem_u32(sm);
    int tid = threadIdx.x, lane = tid & 31, wid = tid >> 5;
    int n0 = blockIdx.x * 256, d0 = blockIdx.y * 128, ks = blockIdx.z;
    int jbase = ks * (RK_ / KSPLIT);
    int wm = (wid >> 2) * 64, wn = (wid & 3) * 32;

    const __nv_bfloat16* Ah = g_chi  + (size_t)n0 * RK_ + jbase;
    const __nv_bfloat16* Al = g_clo  + (size_t)n0 * RK_ + jbase;
    const __nv_bfloat16* Bh = g_ibth + (size_t)d0 * RK_ + jbase;
    const __nv_bfloat16* Bl = g_ibtl + (size_t)d0 * RK_ + jbase;

    float acc[4][4][4];
    #pragma unroll
    for (int a = 0; a < 4; a++)
        #pragma unroll
        for (int b = 0; b < 4; b++)
            #pragma unroll
            for (int c = 0; c < 4; c++) acc[a][b][c] = 0.0f;

    int rw0 = tid >> 3, fch = tid & 7;

    auto fill = [&](int c, int stg) {
        uint32_t b = sbase + stg * STG2_BYTES;
        int j0 = c * 64;
        #pragma unroll
        for (int i = 0; i < 4; i++) {
            int rw = rw0 + 64 * i;
            uint32_t off = SW2(rw, fch);
            size_t so = (size_t)rw * RK_ + j0 + fch * 8;
            cp16(b +       off, Ah + so);
            cp16(b + A2T + off, Al + so);
        }
        #pragma unroll
        for (int i = 0; i < 2; i++) {
            int rw = rw0 + 64 * i;
            uint32_t off = SW2(rw, fch);
            size_t so = (size_t)rw * RK_ + j0 + fch * 8;
            cp16(b + 2 * A2T +       off, Bh + so);
            cp16(b + 2 * A2T + B2T + off, Bl + so);
        }
    };

    auto compute = [&](int stg) {
        uint32_t b = sbase + stg * STG2_BYTES;
        #pragma unroll
        for (int kk = 0; kk < 4; kk++) {
            int lc = kk * 2 + (lane >> 4);
            uint32_t bh[4][2], bl[4][2];
            #pragma unroll
            for (int bi = 0; bi < 2; bi++) {
                int rw = wn + bi * 16 + (lane & 15);
                uint32_t off = SW2(rw, lc);
                uint32_t t[4];
                ldsm4(t, b + 2 * A2T + off);
                bh[2*bi][0] = t[0]; bh[2*bi][1] = t[2];
                bh[2*bi+1][0] = t[1]; bh[2*bi+1][1] = t[3];
                ldsm4(t, b + 2 * A2T + B2T + off);
                bl[2*bi][0] = t[0]; bl[2*bi][1] = t[2];
                bl[2*bi+1][0] = t[1]; bl[2*bi+1][1] = t[3];
            }
            #pragma unroll
            for (int mi = 0; mi < 4; mi++) {
                int rw = wm + mi * 16 + (lane & 15);
                uint32_t off = SW2(rw, lc);
                uint32_t ah[4], al[4];
                ldsm4(ah, b + off);
                ldsm4(al, b + A2T + off);
                #pragma unroll
                for (int ni = 0; ni < 4; ni++) {
                    mma_bf16(acc[mi][ni], ah, bh[ni]);
                    mma_bf16(acc[mi][ni], ah, bl[ni]);
                    mma_bf16(acc[mi][ni], al, bh[ni]);
                }
            }
        }
    };

    const int NC = (RK_ / KSPLIT) / 64;   // 32
    fill(0, 0); CP_COMMIT();
    #pragma unroll 1
    for (int c = 0; c < NC; c++) {
        CP_WAIT0();
        __syncthreads();
        if (c + 1 < NC) { fill(c + 1, (c + 1) & 1); CP_COMMIT(); }
        compute(c & 1);
    }

    int mrow = lane >> 2, kcol = (lane & 3) * 2;
    #pragma unroll
    for (int mi = 0; mi < 4; mi++)
        #pragma unroll
        for (int ni = 0; ni < 4; ni++) {
            int dg = d0 + wn + ni * 8 + kcol;
            int m0 = n0 + wm + mi * 16 + mrow;
            #pragma unroll
            for (int half = 0; half < 2; half++) {
                float2 v = make_float2(acc[mi][ni][half * 2 + 0],
                                       acc[mi][ni][half * 2 + 1]);
                *(float2*)(g_part + ((size_t)ks * N_ + m0 + half * 8) * D_ + dg) = v;
            }
        }
}

// ---------------------------------------------------------------------------
// Final: out[n,d] = sum_a x[n,abl[a],d] + sum_ks part[ks][n][d]  (fused)
// ---------------------------------------------------------------------------
__global__ void reduce_out(const float* __restrict__ x,
                           const int* __restrict__ abl,
                           float* __restrict__ out) {
    __shared__ int sabl[ABL_];
    if (threadIdx.x < ABL_) sabl[threadIdx.x] = abl[threadIdx.x];
    __syncthreads();

    size_t i4 = ((size_t)blockIdx.x * blockDim.x + threadIdx.x) * 4;
    int n = (int)(i4 / D_);
    int d = (int)(i4 - (size_t)n * D_);
    const float* xp = x + (size_t)n * S_ * D_ + d;

    float4 s = make_float4(0.f, 0.f, 0.f, 0.f);
    #pragma unroll
    for (int a = 0; a < ABL_; a++) {
        float4 v = __ldg((const float4*)(xp + (size_t)sabl[a] * D_));
        s.x += v.x; s.y += v.y; s.z += v.z; s.w += v.w;
    }
    #pragma unroll
    for (int ks = 0; ks < KSPLIT; ks++) {
        float4 p = *(const float4*)(g_part + (size_t)ks * N_ * D_ + i4);
        s.x += p.x; s.y += p.y; s.z += p.z; s.w += p.w;
    }
    *(float4*)(out + i4) = s;
}

// ---------------------------------------------------------------------------
// Launch (gemm1 stays the 4th launch -> profiled)
// ---------------------------------------------------------------------------
extern "C" void kernel_launch(void* const* d_in, const int* in_sizes, int n_in,
                              void* d_out, int out_size) {
    const float* x       = (const float*)d_in[0];
    const float* lambdas = (const float*)d_in[1];
    const float* bases   = (const float*)d_in[2];
    const float* invb    = (const float*)d_in[3];
    const float* means   = (const float*)d_in[4];
    const int*   resid   = (const int*)d_in[5];
    const int*   abl     = (const int*)d_in[6];
    const int*   lengths = (const int*)d_in[7];
    float*       out     = (float*)d_out;

    int total_lam = in_sizes[1];

    cudaFuncSetAttribute(gemm1_mma, cudaFuncAttributeMaxDynamicSharedMemorySize, SMEM_G1);
    cudaFuncSetAttribute(gemm2_mma, cudaFuncAttributeMaxDynamicSharedMemorySize, SMEM_G2);

    prep_blam<<<R_, 256>>>(lambdas, bases, means, lengths, total_lam);
    convert_ibt<<<dim3(RK_ / 32, D_ / 32), dim3(32, 8)>>>(invb);
    convert_ibt<<<dim3(1, 1), dim3(32, 8), 0>>>(invb);  // tiny repeat keeps gemm1 4th launch
    gemm1_mma<<<dim3(N_ / 128, R_), 256, SMEM_G1>>>(x, resid);
    gemm2_mma<<<dim3(N_ / 256, D_ / 128, KSPLIT), 512, SMEM_G2>>>();
    reduce_out<<<(N_ * D_ / 4) / 256, 256>>>(x, abl, out);
}

// round 17
// speedup vs baseline: 1.0627x; 1.0078x over previous
#include <cuda_runtime.h>
#include <cuda_bf16.h>
#include <cstdint>

#define N_   1024
#define S_   144
#define R_   96
#define K_   128
#define D_   768
#define ABL_ 48
#define RK_  (R_ * K_)   // 12288
#define KSPLIT 6

// ---------------------------------------------------------------------------
// Device-global scratch
// ---------------------------------------------------------------------------
__device__ float g_c0[RK_];
__device__ __align__(16) __nv_bfloat16 g_blh[(size_t)R_ * K_ * D_];
__device__ __align__(16) __nv_bfloat16 g_bll[(size_t)R_ * K_ * D_];
__device__ __align__(16) __nv_bfloat16 g_chi[(size_t)N_ * RK_];
__device__ __align__(16) __nv_bfloat16 g_clo[(size_t)N_ * RK_];
__device__ __align__(16) __nv_bfloat16 g_ibth[(size_t)D_ * RK_];
__device__ __align__(16) __nv_bfloat16 g_ibtl[(size_t)D_ * RK_];
__device__ float g_part[(size_t)KSPLIT * N_ * D_];

// ---------------------------------------------------------------------------
// Helpers
// ---------------------------------------------------------------------------
__device__ __forceinline__ uint32_t smem_u32(const void* p) {
    uint32_t a;
    asm("{ .reg .u64 t; cvta.to.shared.u64 t, %1; cvt.u32.u64 %0, t; }"
        : "=r"(a) : "l"(p));
    return a;
}

__device__ __forceinline__ void cp16(uint32_t dst, const void* src) {
    asm volatile("cp.async.cg.shared.global [%0], [%1], 16;" :: "r"(dst), "l"(src));
}
#define CP_COMMIT() asm volatile("cp.async.commit_group;" ::: "memory")
#define CP_WAIT1()  asm volatile("cp.async.wait_group 1;"  ::: "memory")
#define CP_WAIT0()  asm volatile("cp.async.wait_group 0;"  ::: "memory")

__device__ __forceinline__ void ldsm4(uint32_t* r, uint32_t a) {
    asm volatile("ldmatrix.sync.aligned.m8n8.x4.shared.b16 {%0,%1,%2,%3}, [%4];"
        : "=r"(r[0]), "=r"(r[1]), "=r"(r[2]), "=r"(r[3]) : "r"(a));
}

__device__ __forceinline__ void mma_bf16(float* d, const uint32_t* a, const uint32_t* b) {
    asm volatile(
        "mma.sync.aligned.m16n8k16.row.col.f32.bf16.bf16.f32 "
        "{%0,%1,%2,%3}, {%4,%5,%6,%7}, {%8,%9}, {%0,%1,%2,%3};"
        : "+f"(d[0]), "+f"(d[1]), "+f"(d[2]), "+f"(d[3])
        : "r"(a[0]), "r"(a[1]), "r"(a[2]), "r"(a[3]), "r"(b[0]), "r"(b[1]));
}

__device__ __forceinline__ void split1(float v, __nv_bfloat16& h, __nv_bfloat16& l) {
    h = __float2bfloat16(v);
    l = __float2bfloat16(v - __bfloat162float(h));
}
__device__ __forceinline__ uint32_t pack2(__nv_bfloat16 a, __nv_bfloat16 b) {
    uint16_t x = *(uint16_t*)&a, y = *(uint16_t*)&b;
    return (uint32_t)x | ((uint32_t)y << 16);
}

// truncation split pair helpers: (v0, v1) -> packed bf16x2 (lo half = v0)
__device__ __forceinline__ uint32_t hi_pair(float v0, float v1) {
    uint32_t r;
    asm("prmt.b32 %0, %1, %2, 0x7632;" : "=r"(r)
        : "r"(__float_as_uint(v0)), "r"(__float_as_uint(v1)));
    return r;
}
__device__ __forceinline__ uint32_t lo_pair(float v0, float v1) {
    float t0 = __uint_as_float(__float_as_uint(v0) & 0xFFFF0000u);
    float t1 = __uint_as_float(__float_as_uint(v1) & 0xFFFF0000u);
    float l0 = v0 - t0, l1 = v1 - t1;
    uint32_t r;
    asm("cvt.rn.bf16x2.f32 %0, %1, %2;" : "=r"(r) : "f"(l1), "f"(l0));
    return r;
}

// 64B-row swizzle (32 bf16/row): phys chunk = ch ^ ((row>>1)&3)
#define SW1(rw, ch4) ((rw) * 64 + (((ch4) ^ (((rw) >> 1) & 3)) << 4))
// 128B-row swizzle (64 bf16/row): phys chunk = ch ^ (row&7)
#define SW2(rw, ch8) ((rw) * 128 + (((ch8) ^ ((rw) & 7)) << 4))

// GEMM1 smem: 128x32 tiles, Ah|Al|Bh|Bl @ 8KB, 3 stages = 96KB, 2 CTAs/SM (192KB)
#define TILE_BYTES 8192
#define STG_BYTES  32768
#define NSTG1 3
#define SMEM_G1 (NSTG1 * STG_BYTES)      // 98304
// GEMM2 smem: A 256x64 (32KB) hi/lo + B 128x64 (16KB) hi/lo, 2 stages
#define A2T 32768
#define B2T 16384
#define STG2_BYTES (2 * A2T + 2 * B2T)   // 98304
#define SMEM_G2 (2 * STG2_BYTES)         // 196608

// ---------------------------------------------------------------------------
// prep + blam convert fused
// ---------------------------------------------------------------------------
__global__ void prep_blam(const float* __restrict__ lambdas,
                          const float* __restrict__ bases,
                          const float* __restrict__ means,
                          const int*   __restrict__ lengths,
                          int total_lam) {
    int r = blockIdx.x, tid = threadIdx.x;

    __shared__ float smean[D_];
    __shared__ float slam[K_];
    __shared__ float sdot[256];

    for (int d = tid; d < D_; d += 256)
        smean[d] = means[r * D_ + d];
    __syncthreads();

    int off = 0;
    for (int i = 0; i < r; i++) off += lengths[i];
    int len = lengths[r];

    int k = tid >> 1, h = tid & 1;
    const float* brow = bases + ((size_t)r * K_ + k) * D_;
    float dot = 0.0f;
    #pragma unroll 8
    for (int d = h * (D_ / 2); d < (h + 1) * (D_ / 2); d++)
        dot += smean[d] * brow[d];
    sdot[tid] = dot;
    __syncthreads();

    if (h == 0) {
        float lam = 0.0f;
        if (k < len) {
            int idx = off + k;
            if (idx > total_lam - 1) idx = total_lam - 1;
            lam = lambdas[idx];
        }
        g_c0[r * K_ + k] = lam * (sdot[tid] + sdot[tid + 1]);
        slam[k] = lam;
    }
    __syncthreads();

    const float* bbase = bases + (size_t)r * K_ * D_;
    for (int i4 = tid * 4; i4 < K_ * D_; i4 += 256 * 4) {
        float lam = slam[i4 / D_];
        float4 v = *(const float4*)(bbase + i4);
        __align__(8) __nv_bfloat16 hh[4], ll[4];
        split1(v.x * lam, hh[0], ll[0]); split1(v.y * lam, hh[1], ll[1]);
        split1(v.z * lam, hh[2], ll[2]); split1(v.w * lam, hh[3], ll[3]);
        size_t o = (size_t)r * K_ * D_ + i4;
        *(uint2*)(g_blh + o) = *(uint2*)hh;
        *(uint2*)(g_bll + o) = *(uint2*)ll;
    }
}

// invb [j][d] -> transposed bf16 hi/lo [d][j]
__global__ void convert_ibt(const float* __restrict__ invb) {
    __shared__ float t[32][33];
    int jb = blockIdx.x * 32, db = blockIdx.y * 32;
    int tx = threadIdx.x, ty = threadIdx.y;  // 32 x 8
    #pragma unroll
    for (int k = 0; k < 4; k++)
        t[ty + 8 * k][tx] = invb[(size_t)(jb + ty + 8 * k) * D_ + db + tx];
    __syncthreads();
    #pragma unroll
    for (int k = 0; k < 4; k++) {
        float v = t[tx][ty + 8 * k];
        __nv_bfloat16 h, l;
        split1(v, h, l);
        size_t o = (size_t)(db + ty + 8 * k) * RK_ + jb + tx;
        g_ibth[o] = h;
        g_ibtl[o] = l;
    }
}

// ---------------------------------------------------------------------------
// GEMM1 (mma.sync bf16x3, fused gather + truncation split, 3-stage commit-ahead)
// Block 128(m) x 128(k) x BK=32. grid=(8, 96), 256 thr, 2 CTAs/SM.
// Pipeline: group for chunk c+2 committed at end of iter c, awaited at iter c+2
// (WAIT1 leaves one group in flight; tail iter uses WAIT0).
// ---------------------------------------------------------------------------
#define G1_NC 24

__global__ __launch_bounds__(256, 2)
void gemm1_mma(const float* __restrict__ x, const int* __restrict__ resid) {
    extern __shared__ __align__(128) char sm[];
    uint32_t sbase = smem_u32(sm);
    int tid = threadIdx.x, lane = tid & 31, wid = tid >> 5;
    int r = blockIdx.y, n0 = blockIdx.x * 128;
    int s = __ldg(resid + r);
    int wm = (wid >> 2) * 64, wn = (wid & 3) * 32;

    const float* Ax = x + ((size_t)n0 * S_ + s) * D_;
    const __nv_bfloat16* Bh = g_blh + (size_t)r * K_ * D_;
    const __nv_bfloat16* Bl = g_bll + (size_t)r * K_ * D_;

    float acc[4][4][4];
    #pragma unroll
    for (int a = 0; a < 4; a++)
        #pragma unroll
        for (int b = 0; b < 4; b++)
            #pragma unroll
            for (int c = 0; c < 4; c++) acc[a][b][c] = 0.0f;

    int frow = tid >> 2, fch = tid & 3;
    float4 ra[4];

    auto ldgA = [&](int c) {
        int d0 = c * 32;
        #pragma unroll
        for (int i = 0; i < 2; i++) {
            int rw = frow + 64 * i;
            const float* p = Ax + (size_t)rw * (S_ * D_) + d0 + fch * 8;
            ra[2 * i]     = __ldg((const float4*)p);
            ra[2 * i + 1] = __ldg((const float4*)(p + 4));
        }
    };

    auto stsA = [&](int stg) {
        char* b = sm + stg * STG_BYTES;
        #pragma unroll
        for (int i = 0; i < 2; i++) {
            int rw = frow + 64 * i;
            uint32_t off = SW1(rw, fch);
            float4 v0 = ra[2 * i], v1 = ra[2 * i + 1];
            uint4 hq = make_uint4(hi_pair(v0.x, v0.y), hi_pair(v0.z, v0.w),
                                  hi_pair(v1.x, v1.y), hi_pair(v1.z, v1.w));
            uint4 lq = make_uint4(lo_pair(v0.x, v0.y), lo_pair(v0.z, v0.w),
                                  lo_pair(v1.x, v1.y), lo_pair(v1.z, v1.w));
            *(uint4*)(b + off)              = hq;
            *(uint4*)(b + TILE_BYTES + off) = lq;
        }
    };

    auto cpB = [&](int c, int stg) {
        uint32_t b = sbase + stg * STG_BYTES;
        int d0 = c * 32;
        #pragma unroll
        for (int i = 0; i < 2; i++) {
            int rw = frow + 64 * i;
            uint32_t off = SW1(rw, fch);
            size_t so = (size_t)rw * D_ + d0 + fch * 8;
            cp16(b + 2 * TILE_BYTES + off, Bh + so);
            cp16(b + 3 * TILE_BYTES + off, Bl + so);
        }
    };

    auto compute = [&](int stg) {
        uint32_t b = sbase + stg * STG_BYTES;
        #pragma unroll
        for (int kk = 0; kk < 2; kk++) {
            int lc = kk * 2 + (lane >> 4);
            uint32_t bh[4][2], bl[4][2];
            #pragma unroll
            for (int bi = 0; bi < 2; bi++) {
                int rw = wn + bi * 16 + (lane & 15);
                uint32_t off = SW1(rw, lc);
                uint32_t t[4];
                ldsm4(t, b + 2 * TILE_BYTES + off);
                bh[2*bi][0] = t[0]; bh[2*bi][1] = t[2];
                bh[2*bi+1][0] = t[1]; bh[2*bi+1][1] = t[3];
                ldsm4(t, b + 3 * TILE_BYTES + off);
                bl[2*bi][0] = t[0]; bl[2*bi][1] = t[2];
                bl[2*bi+1][0] = t[1]; bl[2*bi+1][1] = t[3];
            }
            #pragma unroll
            for (int mi = 0; mi < 4; mi++) {
                int rw = wm + mi * 16 + (lane & 15);
                uint32_t off = SW1(rw, lc);
                uint32_t ah[4], al[4];
                ldsm4(ah, b + off);
                ldsm4(al, b + TILE_BYTES + off);
                #pragma unroll
                for (int ni = 0; ni < 4; ni++) {
                    mma_bf16(acc[mi][ni], ah, bh[ni]);
                    mma_bf16(acc[mi][ni], ah, bl[ni]);
                    mma_bf16(acc[mi][ni], al, bh[ni]);
                }
            }
        }
    };

    // prologue: stages 0 and 1 filled; regs hold chunk 2
    ldgA(0); stsA(0); cpB(0, 0); CP_COMMIT();
    ldgA(1); stsA(1); cpB(1, 1); CP_COMMIT();
    ldgA(2);

    #pragma unroll 1
    for (int c = 0; c < G1_NC; c++) {
        // drain group for chunk c (WAIT1 leaves chunk c+1's group in flight)
        if (c == G1_NC - 1) { CP_WAIT0(); } else { CP_WAIT1(); }
        __syncthreads();     // all warps done with stage (c+2)%3's previous use
        compute(c % NSTG1);
        if (c + 2 < G1_NC) {
            int stg = (c + 2) % NSTG1;
            stsA(stg);                    // regs from ldgA(c+2)
            cpB(c + 2, stg); CP_COMMIT();
            if (c + 3 < G1_NC) ldgA(c + 3);
        }
    }

    int mrow = lane >> 2, kcol = (lane & 3) * 2;
    #pragma unroll
    for (int mi = 0; mi < 4; mi++)
        #pragma unroll
        for (int ni = 0; ni < 4; ni++) {
            int kg = wn + ni * 8 + kcol;
            float c00 = g_c0[r * K_ + kg], c01 = g_c0[r * K_ + kg + 1];
            int m0 = n0 + wm + mi * 16 + mrow;
            #pragma unroll
            for (int half = 0; half < 2; half++) {
                float v0 = acc[mi][ni][half * 2 + 0] - c00;
                float v1 = acc[mi][ni][half * 2 + 1] - c01;
                __nv_bfloat16 h0, l0, h1, l1;
                split1(v0, h0, l0);
                split1(v1, h1, l1);
                size_t o = (size_t)(m0 + half * 8) * RK_ + r * K_ + kg;
                *(uint32_t*)(g_chi + o) = pack2(h0, h1);
                *(uint32_t*)(g_clo + o) = pack2(l0, l1);
            }
        }
}

// ---------------------------------------------------------------------------
// GEMM2 (mma.sync bf16x3): BK=64, 2-stage, one sync per chunk.
// Block 256(n) x 128(d), split-K=6. grid=(4,6,6)=144 CTAs. 512 thr.
// ---------------------------------------------------------------------------
__global__ __launch_bounds__(512)
void gemm2_mma() {
    extern __shared__ __align__(128) char sm[];
    uint32_t sbase = smem_u32(sm);
    int tid = threadIdx.x, lane = tid & 31, wid = tid >> 5;
    int n0 = blockIdx.x * 256, d0 = blockIdx.y * 128, ks = blockIdx.z;
    int jbase = ks * (RK_ / KSPLIT);
    int wm = (wid >> 2) * 64, wn = (wid & 3) * 32;

    const __nv_bfloat16* Ah = g_chi  + (size_t)n0 * RK_ + jbase;
    const __nv_bfloat16* Al = g_clo  + (size_t)n0 * RK_ + jbase;
    const __nv_bfloat16* Bh = g_ibth + (size_t)d0 * RK_ + jbase;
    const __nv_bfloat16* Bl = g_ibtl + (size_t)d0 * RK_ + jbase;

    float acc[4][4][4];
    #pragma unroll
    for (int a = 0; a < 4; a++)
        #pragma unroll
        for (int b = 0; b < 4; b++)
            #pragma unroll
            for (int c = 0; c < 4; c++) acc[a][b][c] = 0.0f;

    int rw0 = tid >> 3, fch = tid & 7;

    auto fill = [&](int c, int stg) {
        uint32_t b = sbase + stg * STG2_BYTES;
        int j0 = c * 64;
        #pragma unroll
        for (int i = 0; i < 4; i++) {
            int rw = rw0 + 64 * i;
            uint32_t off = SW2(rw, fch);
            size_t so = (size_t)rw * RK_ + j0 + fch * 8;
            cp16(b +       off, Ah + so);
            cp16(b + A2T + off, Al + so);
        }
        #pragma unroll
        for (int i = 0; i < 2; i++) {
            int rw = rw0 + 64 * i;
            uint32_t off = SW2(rw, fch);
            size_t so = (size_t)rw * RK_ + j0 + fch * 8;
            cp16(b + 2 * A2T +       off, Bh + so);
            cp16(b + 2 * A2T + B2T + off, Bl + so);
        }
    };

    auto compute = [&](int stg) {
        uint32_t b = sbase + stg * STG2_BYTES;
        #pragma unroll
        for (int kk = 0; kk < 4; kk++) {
            int lc = kk * 2 + (lane >> 4);
            uint32_t bh[4][2], bl[4][2];
            #pragma unroll
            for (int bi = 0; bi < 2; bi++) {
                int rw = wn + bi * 16 + (lane & 15);
                uint32_t off = SW2(rw, lc);
                uint32_t t[4];
                ldsm4(t, b + 2 * A2T + off);
                bh[2*bi][0] = t[0]; bh[2*bi][1] = t[2];
                bh[2*bi+1][0] = t[1]; bh[2*bi+1][1] = t[3];
                ldsm4(t, b + 2 * A2T + B2T + off);
                bl[2*bi][0] = t[0]; bl[2*bi][1] = t[2];
                bl[2*bi+1][0] = t[1]; bl[2*bi+1][1] = t[3];
            }
            #pragma unroll
            for (int mi = 0; mi < 4; mi++) {
                int rw = wm + mi * 16 + (lane & 15);
                uint32_t off = SW2(rw, lc);
                uint32_t ah[4], al[4];
                ldsm4(ah, b + off);
                ldsm4(al, b + A2T + off);
                #pragma unroll
                for (int ni = 0; ni < 4; ni++) {
                    mma_bf16(acc[mi][ni], ah, bh[ni]);
                    mma_bf16(acc[mi][ni], ah, bl[ni]);
                    mma_bf16(acc[mi][ni], al, bh[ni]);
                }
            }
        }
    };

    const int NC = (RK_ / KSPLIT) / 64;   // 32
    fill(0, 0); CP_COMMIT();
    #pragma unroll 1
    for (int c = 0; c < NC; c++) {
        CP_WAIT0();
        __syncthreads();
        if (c + 1 < NC) { fill(c + 1, (c + 1) & 1); CP_COMMIT(); }
        compute(c & 1);
    }

    int mrow = lane >> 2, kcol = (lane & 3) * 2;
    #pragma unroll
    for (int mi = 0; mi < 4; mi++)
        #pragma unroll
        for (int ni = 0; ni < 4; ni++) {
            int dg = d0 + wn + ni * 8 + kcol;
            int m0 = n0 + wm + mi * 16 + mrow;
            #pragma unroll
            for (int half = 0; half < 2; half++) {
                float2 v = make_float2(acc[mi][ni][half * 2 + 0],
                                       acc[mi][ni][half * 2 + 1]);
                *(float2*)(g_part + ((size_t)ks * N_ + m0 + half * 8) * D_ + dg) = v;
            }
        }
}

// ---------------------------------------------------------------------------
// Final: out[n,d] = sum_a x[n,abl[a],d] + sum_ks part[ks][n][d]  (fused)
// ---------------------------------------------------------------------------
__global__ void reduce_out(const float* __restrict__ x,
                           const int* __restrict__ abl,
                           float* __restrict__ out) {
    __shared__ int sabl[ABL_];
    if (threadIdx.x < ABL_) sabl[threadIdx.x] = abl[threadIdx.x];
    __syncthreads();

    size_t i4 = ((size_t)blockIdx.x * blockDim.x + threadIdx.x) * 4;
    int n = (int)(i4 / D_);
    int d = (int)(i4 - (size_t)n * D_);
    const float* xp = x + (size_t)n * S_ * D_ + d;

    float4 s = make_float4(0.f, 0.f, 0.f, 0.f);
    #pragma unroll
    for (int a = 0; a < ABL_; a++) {
        float4 v = __ldg((const float4*)(xp + (size_t)sabl[a] * D_));
        s.x += v.x; s.y += v.y; s.z += v.z; s.w += v.w;
    }
    #pragma unroll
    for (int ks = 0; ks < KSPLIT; ks++) {
        float4 p = *(const float4*)(g_part + (size_t)ks * N_ * D_ + i4);
        s.x += p.x; s.y += p.y; s.z += p.z; s.w += p.w;
    }
    *(float4*)(out + i4) = s;
}

// ---------------------------------------------------------------------------
// Launch (gemm2 is now the 4th launch -> profiled this round)
// ---------------------------------------------------------------------------
extern "C" void kernel_launch(void* const* d_in, const int* in_sizes, int n_in,
                              void* d_out, int out_size) {
    const float* x       = (const float*)d_in[0];
    const float* lambdas = (const float*)d_in[1];
    const float* bases   = (const float*)d_in[2];
    const float* invb    = (const float*)d_in[3];
    const float* means   = (const float*)d_in[4];
    const int*   resid   = (const int*)d_in[5];
    const int*   abl     = (const int*)d_in[6];
    const int*   lengths = (const int*)d_in[7];
    float*       out     = (float*)d_out;

    int total_lam = in_sizes[1];

    cudaFuncSetAttribute(gemm1_mma, cudaFuncAttributeMaxDynamicSharedMemorySize, SMEM_G1);
    cudaFuncSetAttribute(gemm2_mma, cudaFuncAttributeMaxDynamicSharedMemorySize, SMEM_G2);

    prep_blam<<<R_, 256>>>(lambdas, bases, means, lengths, total_lam);
    convert_ibt<<<dim3(RK_ / 32, D_ / 32), dim3(32, 8)>>>(invb);
    gemm1_mma<<<dim3(N_ / 128, R_), 256, SMEM_G1>>>(x, resid);
    gemm2_mma<<<dim3(N_ / 256, D_ / 128, KSPLIT), 512, SMEM_G2>>>();
    reduce_out<<<(N_ * D_ / 4) / 256, 256>>>(x, abl, out);
}